// round 16
// baseline (speedup 1.0000x reference)
#include <cuda_runtime.h>
#include <cuda_fp16.h>

#define N_NODES 100000
#define N_EDGES 1200000
#define DIM 64

// Scratch (cudaMalloc is forbidden).
__device__ float  g_agg[(size_t)N_NODES * DIM];
__device__ float  g_deg[N_NODES];
__device__ __half g_xh[(size_t)N_NODES * DIM];   // fp16 shadow of x (gather src)
__device__ int    g_idx64;   // 1 if edge_index is int64, 0 if int32

// ---------------------------------------------------------------------------
// f32x2 packed helpers (sm_103; ptxas never auto-fuses these from C++)
// ---------------------------------------------------------------------------
__device__ __forceinline__ unsigned long long ffma2(unsigned long long a,
                                                    unsigned long long b,
                                                    unsigned long long c) {
    unsigned long long d;
    asm("fma.rn.f32x2 %0, %1, %2, %3;" : "=l"(d) : "l"(a), "l"(b), "l"(c));
    return d;
}
__device__ __forceinline__ float2 unpack2(unsigned long long a) {
    float2 r;
    asm("mov.b64 {%0, %1}, %2;" : "=f"(r.x), "=f"(r.y) : "l"(a));
    return r;
}

// ---------------------------------------------------------------------------
// Kernel 1: zero scratch + dtype detect + build fp16 shadow of x.
// ---------------------------------------------------------------------------
__global__ void zero_kernel(const float* __restrict__ x,
                            const int* __restrict__ ei32) {
    if (blockIdx.x == 0 && threadIdx.x == 0) {
        int nz_odd = 0;
        for (int k = 0; k < 128; k++) nz_odd += (ei32[2 * k + 1] != 0);
        g_idx64 = (nz_odd == 0) ? 1 : 0;
    }
    const int stride = gridDim.x * blockDim.x;
    int t = blockIdx.x * blockDim.x + threadIdx.x;
    const int total4 = N_NODES * DIM / 4;   // 1.6M

    float4* agg4 = reinterpret_cast<float4*>(g_agg);
    const float4* x4 = reinterpret_cast<const float4*>(x);
    uint2* xh4 = reinterpret_cast<uint2*>(g_xh);

    for (int i = t; i < total4; i += stride) {
        agg4[i] = make_float4(0.f, 0.f, 0.f, 0.f);
        float4 v = x4[i];
        __half2 a = __floats2half2_rn(v.x, v.y);
        __half2 b = __floats2half2_rn(v.z, v.w);
        uint2 o;
        o.x = *reinterpret_cast<unsigned*>(&a);
        o.y = *reinterpret_cast<unsigned*>(&b);
        xh4[i] = o;
    }
    for (int i = t; i < N_NODES; i += stride)
        g_deg[i] = 0.f;
}

// ---------------------------------------------------------------------------
// Kernel 2: edge scatter. 16 threads/edge; gather fp16 (8B/thread), RED fp32.
// ---------------------------------------------------------------------------
__global__ void edge_kernel(const void* __restrict__ ei_raw) {
    long long t = (long long)blockIdx.x * blockDim.x + threadIdx.x;
    int e = (int)(t >> 4);
    int c = (int)(t & 15);
    if (e >= N_EDGES) return;

    long long i, j;
    if (g_idx64) {
        const long long* ei = (const long long*)ei_raw;
        i = ei[e];
        j = ei[N_EDGES + e];
    } else {
        const int* ei = (const int*)ei_raw;
        i = ei[e];
        j = ei[N_EDGES + e];
    }

    const uint2* xr = reinterpret_cast<const uint2*>(g_xh + j * DIM);
    uint2 p = xr[c];                       // 4 halves, 8 B
    __half2 h0 = *reinterpret_cast<__half2*>(&p.x);
    __half2 h1 = *reinterpret_cast<__half2*>(&p.y);
    float2 f0 = __half22float2(h0);
    float2 f1 = __half22float2(h1);

    float* dst = g_agg + i * DIM + c * 4;
    asm volatile("red.global.add.v4.f32 [%0], {%1, %2, %3, %4};"
                 :: "l"(dst), "f"(f0.x), "f"(f0.y), "f"(f1.x), "f"(f1.y)
                 : "memory");
    if (c == 0) {
        atomicAdd(g_deg + i, 1.0f);
    }
}

// ---------------------------------------------------------------------------
// Kernel 3: register-blocked GEMM + ReLU + LayerNorm  (R12-proven).
// CTA: 256 threads, 64 nodes (3 CTAs/SM). Lane role: cg = tid&15 -> cols
// {cg, cg+16, cg+32, cg+48}; ng = (tid>>4)&1 -> node half (TM=4 nodes).
// ---------------------------------------------------------------------------
#define TM 4
#define NODES_PER_CTA 64
#define WPAD 132   // 528 B row stride: 16B-aligned

__global__ __launch_bounds__(256, 3)
void node_kernel(const float* __restrict__ x,
                 const float* __restrict__ W,      // [64][128]
                 const float* __restrict__ bias,   // [64]
                 const float* __restrict__ gamma,  // [64]
                 const float* __restrict__ beta,   // [64]
                 float* __restrict__ out) {
    extern __shared__ float sm[];
    float* Wsh   = sm;                           // [64][WPAD]
    float* insh  = sm + 64 * WPAD;               // [64][128]
    float* shinv = insh + NODES_PER_CTA * 128;   // [64]

    const int tid  = threadIdx.x;
    const int base = blockIdx.x * NODES_PER_CTA;

    // Stage W (coalesced global read, row-padded shared write)
    for (int i = tid; i < 64 * 32; i += 256) {
        int c = i >> 5, kq = i & 31;
        *reinterpret_cast<float4*>(&Wsh[c * WPAD + kq * 4]) =
            reinterpret_cast<const float4*>(W)[i];
    }
    // Stage inverse degrees
    if (tid < NODES_PER_CTA) {
        int gn = base + tid;
        if (gn >= N_NODES) gn = N_NODES - 1;
        shinv[tid] = 1.0f / fmaxf(g_deg[gn], 1.0f);
    }
    __syncthreads();

    // Stage concat inputs: insh[n][0:64]=x[n], insh[n][64:128]=agg[n]*inv
    for (int i = tid; i < NODES_PER_CTA * 32; i += 256) {
        int n = i >> 5, kq = i & 31;
        int gn = base + n;
        if (gn >= N_NODES) gn = N_NODES - 1;   // clamp (harmless, deterministic)
        float4 v;
        if (kq < 16) {
            v = reinterpret_cast<const float4*>(x + (size_t)gn * DIM)[kq];
        } else {
            v = reinterpret_cast<const float4*>(g_agg + (size_t)gn * DIM)[kq - 16];
            float inv = shinv[n];
            v.x *= inv; v.y *= inv; v.z *= inv; v.w *= inv;
        }
        *reinterpret_cast<float4*>(&insh[n * 128 + kq * 4]) = v;
    }
    __syncthreads();

    const int cg   = tid & 15;          // column group: cols cg + 16*t
    const int ng   = (tid >> 4) & 1;    // node half within warp
    const int warp = tid >> 5;
    const int nodeBase = warp * 8 + ng * TM;   // within CTA

    unsigned long long acc[4][TM];
    #pragma unroll
    for (int t = 0; t < 4; t++)
        #pragma unroll
        for (int m = 0; m < TM; m++) acc[t][m] = 0ull;

    const float* ip  = insh + nodeBase * 128;
    const float* wp0 = Wsh + (cg +  0) * WPAD;
    const float* wp1 = Wsh + (cg + 16) * WPAD;
    const float* wp2 = Wsh + (cg + 32) * WPAD;
    const float* wp3 = Wsh + (cg + 48) * WPAD;

    #pragma unroll 4
    for (int kq = 0; kq < 32; kq++) {
        ulonglong2 w0 = *reinterpret_cast<const ulonglong2*>(wp0 + kq * 4);
        ulonglong2 w1 = *reinterpret_cast<const ulonglong2*>(wp1 + kq * 4);
        ulonglong2 w2 = *reinterpret_cast<const ulonglong2*>(wp2 + kq * 4);
        ulonglong2 w3 = *reinterpret_cast<const ulonglong2*>(wp3 + kq * 4);
        #pragma unroll
        for (int m = 0; m < TM; m++) {
            ulonglong2 iv = *reinterpret_cast<const ulonglong2*>(ip + m * 128 + kq * 4);
            acc[0][m] = ffma2(iv.x, w0.x, acc[0][m]);
            acc[0][m] = ffma2(iv.y, w0.y, acc[0][m]);
            acc[1][m] = ffma2(iv.x, w1.x, acc[1][m]);
            acc[1][m] = ffma2(iv.y, w1.y, acc[1][m]);
            acc[2][m] = ffma2(iv.x, w2.x, acc[2][m]);
            acc[2][m] = ffma2(iv.y, w2.y, acc[2][m]);
            acc[3][m] = ffma2(iv.x, w3.x, acc[3][m]);
            acc[3][m] = ffma2(iv.y, w3.y, acc[3][m]);
        }
    }

    // Epilogue: halves + bias -> ReLU; LayerNorm over the 16-lane col group.
    float bi[4];
    #pragma unroll
    for (int t = 0; t < 4; t++) bi[t] = bias[cg + 16 * t];

    float h[4][TM], sv[TM], qv[TM];
    #pragma unroll
    for (int m = 0; m < TM; m++) {
        float s = 0.f, q = 0.f;
        #pragma unroll
        for (int t = 0; t < 4; t++) {
            float2 a = unpack2(acc[t][m]);
            float v = fmaxf(a.x + a.y + bi[t], 0.f);
            h[t][m] = v;
            s += v;
            q += v * v;
        }
        sv[m] = s; qv[m] = q;
    }
    #pragma unroll
    for (int off = 8; off > 0; off >>= 1) {       // xor<16: stays within group
        #pragma unroll
        for (int m = 0; m < TM; m++) {
            sv[m] += __shfl_xor_sync(0xFFFFFFFFu, sv[m], off);
            qv[m] += __shfl_xor_sync(0xFFFFFFFFu, qv[m], off);
        }
    }

    float ga[4], be[4];
    #pragma unroll
    for (int t = 0; t < 4; t++) {
        ga[t] = gamma[cg + 16 * t];
        be[t] = beta[cg + 16 * t];
    }
    #pragma unroll
    for (int m = 0; m < TM; m++) {
        int gn = base + nodeBase + m;
        if (gn < N_NODES) {
            float mu   = sv[m] * (1.0f / DIM);
            float var  = qv[m] * (1.0f / DIM) - mu * mu;
            float rstd = rsqrtf(var + 1e-5f);
            float* op = out + (size_t)gn * DIM + cg;
            #pragma unroll
            for (int t = 0; t < 4; t++)
                op[16 * t] = (h[t][m] - mu) * rstd * ga[t] + be[t];
        }
    }
}

// ---------------------------------------------------------------------------
extern "C" void kernel_launch(void* const* d_in, const int* in_sizes, int n_in,
                              void* d_out, int out_size) {
    const float* x     = (const float*)d_in[0];   // [100000, 64]
    const float* W     = (const float*)d_in[1];   // [64, 128]
    const float* bias  = (const float*)d_in[2];   // [64]
    const float* gamma = (const float*)d_in[3];   // [64]
    const float* beta  = (const float*)d_in[4];   // [64]
    const void*  ei    = d_in[5];                 // [2, 1200000] int32 or int64
    float* out         = (float*)d_out;

    // 1) zero scratch + dtype detect + fp16 shadow of x
    zero_kernel<<<2048, 256>>>(x, (const int*)ei);

    // 2) edge scatter: 16 threads per edge, fp16 gather / fp32 RED
    {
        long long threads = (long long)N_EDGES * 16;
        int blocks = (int)((threads + 255) / 256);
        edge_kernel<<<blocks, 256>>>(ei);
    }

    // 3) node phase: 4-col register-blocked GEMM + LN, 3 CTAs/SM
    {
        int smem = (64 * WPAD + NODES_PER_CTA * 128 + NODES_PER_CTA) * sizeof(float);
        cudaFuncSetAttribute(node_kernel,
                             cudaFuncAttributeMaxDynamicSharedMemorySize, smem);
        int blocks = (N_NODES + NODES_PER_CTA - 1) / NODES_PER_CTA;  // 1563
        node_kernel<<<blocks, 256, smem>>>(x, W, bias, gamma, beta, out);
    }
}